// round 2
// baseline (speedup 1.0000x reference)
#include <cuda_runtime.h>
#include <cstdint>

#define B_  8
#define H_  8
#define NQ_ 1024
#define NKV_ 2048
#define D_  512
#define HD_ 64

// ---------------- scratch (static __device__, no allocs) ----------------
__device__ float g_Q [B_ * H_ * NQ_  * HD_];   // 16 MB
__device__ float g_K [B_ * H_ * NKV_ * HD_];   // 32 MB
__device__ float g_V [B_ * H_ * NKV_ * HD_];   // 32 MB
__device__ float g_AO[B_ * NQ_ * D_];          // 16 MB

// ---------------- PTX helpers ----------------
__device__ __forceinline__ uint32_t f2tf32(float x) {
    uint32_t r;
    asm("cvt.rna.tf32.f32 %0, %1;" : "=r"(r) : "f"(x));
    return r;
}

__device__ __forceinline__ void mma_tf32(float* c, const uint32_t* a, uint32_t b0, uint32_t b1) {
    asm volatile(
        "mma.sync.aligned.m16n8k8.row.col.f32.tf32.tf32.f32 "
        "{%0,%1,%2,%3}, {%4,%5,%6,%7}, {%8,%9}, {%0,%1,%2,%3};"
        : "+f"(c[0]), "+f"(c[1]), "+f"(c[2]), "+f"(c[3])
        : "r"(a[0]), "r"(a[1]), "r"(a[2]), "r"(a[3]), "r"(b0), "r"(b1));
}

__device__ __forceinline__ void cp16(void* dst, const void* src) {
    uint32_t d = (uint32_t)__cvta_generic_to_shared(dst);
    asm volatile("cp.async.cg.shared.global [%0], [%1], 16;" :: "r"(d), "l"(src));
}
#define CP_COMMIT() asm volatile("cp.async.commit_group;")

// =======================================================================
// GEMM: out[m][n] = sum_k A[m][k] * W[n][k]   (M x 512 @ 512 x 512)
// A row-major [M][512], W row-major [512][512] (acts as col-major B).
// DST: 0 -> g_Q (head-split scatter), 1 -> g_K, 2 -> g_V, 3 -> plain out param.
// =======================================================================
#define GSTR 36   // 128x32 tile, stride 36 floats -> conflict-free frags

template<int DST>
__global__ __launch_bounds__(256, 2)
void gemm_tf32(const float* __restrict__ A, const float* __restrict__ W,
               float* __restrict__ out_param, int M, int Nseq)
{
    extern __shared__ float sm[];
    float* Asb[2] = { sm,              sm + 128 * GSTR };
    float* Bsb[2] = { sm + 2*128*GSTR, sm + 3*128*GSTR };

    const int tid  = threadIdx.x;
    const int lane = tid & 31;
    const int wid  = tid >> 5;
    const int wm   = wid >> 2;       // 0..1
    const int wn   = wid & 3;        // 0..3
    const int m0   = blockIdx.y * 128;
    const int n0   = blockIdx.x * 128;

    float* out = (DST == 0) ? g_Q : (DST == 1) ? g_K : (DST == 2) ? g_V : out_param;

    float acc[4][4][4];
    #pragma unroll
    for (int i = 0; i < 4; i++)
        #pragma unroll
        for (int j = 0; j < 4; j++)
            #pragma unroll
            for (int r = 0; r < 4; r++) acc[i][j][r] = 0.f;

    auto load_tiles = [&](int buf, int kt) {
        const float* Ag = A + (size_t)m0 * 512 + kt * 32;
        const float* Wg = W + (size_t)n0 * 512 + kt * 32;
        #pragma unroll
        for (int i = 0; i < 4; i++) {
            int idx = tid + i * 256;
            int row = idx >> 3, seg = idx & 7;
            cp16(&Asb[buf][row * GSTR + seg * 4], Ag + (size_t)row * 512 + seg * 4);
        }
        #pragma unroll
        for (int i = 0; i < 4; i++) {
            int idx = tid + i * 256;
            int row = idx >> 3, seg = idx & 7;
            cp16(&Bsb[buf][row * GSTR + seg * 4], Wg + (size_t)row * 512 + seg * 4);
        }
        CP_COMMIT();
    };

    load_tiles(0, 0);

    for (int kt = 0; kt < 16; kt++) {
        const int buf = kt & 1;
        if (kt + 1 < 16) {
            load_tiles(buf ^ 1, kt + 1);
            asm volatile("cp.async.wait_group 1;");
        } else {
            asm volatile("cp.async.wait_group 0;");
        }
        __syncthreads();

        const float* a_s = Asb[buf];
        const float* b_s = Bsb[buf];
        #pragma unroll
        for (int ks = 0; ks < 4; ks++) {
            uint32_t af[4][4], bf[4][2];
            const int c = ks * 8 + (lane & 3);
            #pragma unroll
            for (int ma = 0; ma < 4; ma++) {
                const int r = wm * 64 + ma * 16 + (lane >> 2);
                af[ma][0] = f2tf32(a_s[r * GSTR + c]);
                af[ma][1] = f2tf32(a_s[(r + 8) * GSTR + c]);
                af[ma][2] = f2tf32(a_s[r * GSTR + c + 4]);
                af[ma][3] = f2tf32(a_s[(r + 8) * GSTR + c + 4]);
            }
            #pragma unroll
            for (int na = 0; na < 4; na++) {
                const int nn = wn * 32 + na * 8 + (lane >> 2);
                bf[na][0] = f2tf32(b_s[nn * GSTR + c]);
                bf[na][1] = f2tf32(b_s[nn * GSTR + c + 4]);
            }
            #pragma unroll
            for (int ma = 0; ma < 4; ma++)
                #pragma unroll
                for (int na = 0; na < 4; na++)
                    mma_tf32(acc[ma][na], af[ma], bf[na][0], bf[na][1]);
        }
        __syncthreads();
    }

    // epilogue
    #pragma unroll
    for (int ma = 0; ma < 4; ma++) {
        #pragma unroll
        for (int na = 0; na < 4; na++) {
            const int m = m0 + wm * 64 + ma * 16 + (lane >> 2);
            const int n = n0 + wn * 32 + na * 8 + 2 * (lane & 3);
            const float* a = acc[ma][na];
            if (DST != 3) {
                const int bb = m / Nseq;
                const int nn = m - bb * Nseq;
                const int h  = n >> 6;
                const int hd = n & 63;
                float* base = out + (((size_t)bb * H_ + h) * Nseq) * HD_;
                *(float2*)(base + (size_t)nn * HD_ + hd)       = make_float2(a[0], a[1]);
                *(float2*)(base + (size_t)(nn + 8) * HD_ + hd) = make_float2(a[2], a[3]);
            } else {
                *(float2*)(out + (size_t)m * 512 + n)       = make_float2(a[0], a[1]);
                *(float2*)(out + (size_t)(m + 8) * 512 + n) = make_float2(a[2], a[3]);
            }
        }
    }
}

// =======================================================================
// Flash attention with additive bias.
// CTA: one (b, h, q-tile of 128). 8 warps; warp w owns S/O rows [16w, 16w+16).
// KV tile = 64. Online softmax over 32 tiles. TF32 MMA for QK^T and PV.
// =======================================================================
#define QSTR 68
#define KSTR 68
#define VSTR 72
#define PSTR 68
#define ATT_SMEM_FLOATS (128*QSTR + 64*KSTR + 64*VSTR + 128*PSTR)

__global__ __launch_bounds__(256, 2)
void attn_tf32(const float* __restrict__ pos_bias)
{
    extern __shared__ float sm[];
    float*    Qs = sm;
    float*    Ks = Qs + 128 * QSTR;
    float*    Vs = Ks + 64 * KSTR;
    float*    Ps = Vs + 64 * VSTR;
    uint32_t* Pu = (uint32_t*)Ps;

    const int tid  = threadIdx.x;
    const int lane = tid & 31;
    const int wid  = tid >> 5;

    const int bx = blockIdx.x;
    const int qt = bx & 7;
    const int h  = (bx >> 3) & 7;
    const int b  = bx >> 6;

    const int q0 = qt * 128 + wid * 16 + (lane >> 2);   // this thread's first S row

    // O accumulators: 16 rows x 64 cols per warp -> 8 n-atoms
    float o[8][4];
    #pragma unroll
    for (int na = 0; na < 8; na++)
        #pragma unroll
        for (int r = 0; r < 4; r++) o[na][r] = 0.f;
    float m_0 = -1e30f, m_1 = -1e30f, l_0 = 0.f, l_1 = 0.f;

    // load Q tile (128 x 64) once
    {
        const float* Qg = g_Q + (((size_t)b * H_ + h) * NQ_ + (size_t)qt * 128) * HD_;
        #pragma unroll
        for (int i = 0; i < 8; i++) {
            int idx = tid + i * 256;
            int row = idx >> 4, seg = idx & 15;
            cp16(&Qs[row * QSTR + seg * 4], Qg + (size_t)row * HD_ + seg * 4);
        }
        CP_COMMIT();
    }

    const float* Kg0 = g_K + (((size_t)b * H_ + h) * NKV_) * HD_;
    const float* Vg0 = g_V + (((size_t)b * H_ + h) * NKV_) * HD_;

    for (int kvt = 0; kvt < NKV_ / 64; kvt++) {
        // load K, V tiles (64 x 64 each)
        {
            const float* Kg = Kg0 + (size_t)kvt * 64 * HD_;
            const float* Vg = Vg0 + (size_t)kvt * 64 * HD_;
            #pragma unroll
            for (int i = 0; i < 4; i++) {
                int idx = tid + i * 256;
                int row = idx >> 4, seg = idx & 15;
                cp16(&Ks[row * KSTR + seg * 4], Kg + (size_t)row * HD_ + seg * 4);
            }
            #pragma unroll
            for (int i = 0; i < 4; i++) {
                int idx = tid + i * 256;
                int row = idx >> 4, seg = idx & 15;
                cp16(&Vs[row * VSTR + seg * 4], Vg + (size_t)row * HD_ + seg * 4);
            }
            CP_COMMIT();
        }
        asm volatile("cp.async.wait_group 0;");
        __syncthreads();

        // ---- S = Q @ K^T  (16 x 64 per warp) ----
        float s[8][4];
        #pragma unroll
        for (int na = 0; na < 8; na++)
            #pragma unroll
            for (int r = 0; r < 4; r++) s[na][r] = 0.f;

        const int rloc = wid * 16 + (lane >> 2);
        #pragma unroll
        for (int ks = 0; ks < 8; ks++) {
            const int c = ks * 8 + (lane & 3);
            uint32_t qa[4];
            qa[0] = f2tf32(Qs[rloc * QSTR + c]);
            qa[1] = f2tf32(Qs[(rloc + 8) * QSTR + c]);
            qa[2] = f2tf32(Qs[rloc * QSTR + c + 4]);
            qa[3] = f2tf32(Qs[(rloc + 8) * QSTR + c + 4]);
            #pragma unroll
            for (int na = 0; na < 8; na++) {
                const int nn = na * 8 + (lane >> 2);
                uint32_t b0 = f2tf32(Ks[nn * KSTR + c]);
                uint32_t b1 = f2tf32(Ks[nn * KSTR + c + 4]);
                mma_tf32(s[na], qa, b0, b1);
            }
        }

        // ---- add bias ----
        {
            const float* bias_base = pos_bias + ((size_t)h * NQ_ + q0) * NKV_ + (size_t)kvt * 64;
            #pragma unroll
            for (int na = 0; na < 8; na++) {
                const int cb = na * 8 + 2 * (lane & 3);
                float2 blo = *(const float2*)(bias_base + cb);
                float2 bhi = *(const float2*)(bias_base + (size_t)8 * NKV_ + cb);
                s[na][0] += blo.x; s[na][1] += blo.y;
                s[na][2] += bhi.x; s[na][3] += bhi.y;
            }
        }

        // ---- online softmax ----
        float rmax0 = -1e30f, rmax1 = -1e30f;
        #pragma unroll
        for (int na = 0; na < 8; na++) {
            rmax0 = fmaxf(rmax0, fmaxf(s[na][0], s[na][1]));
            rmax1 = fmaxf(rmax1, fmaxf(s[na][2], s[na][3]));
        }
        rmax0 = fmaxf(rmax0, __shfl_xor_sync(0xffffffffu, rmax0, 1));
        rmax0 = fmaxf(rmax0, __shfl_xor_sync(0xffffffffu, rmax0, 2));
        rmax1 = fmaxf(rmax1, __shfl_xor_sync(0xffffffffu, rmax1, 1));
        rmax1 = fmaxf(rmax1, __shfl_xor_sync(0xffffffffu, rmax1, 2));

        const float mn0 = fmaxf(m_0, rmax0);
        const float mn1 = fmaxf(m_1, rmax1);
        const float al0 = __expf(m_0 - mn0);
        const float al1 = __expf(m_1 - mn1);
        m_0 = mn0; m_1 = mn1;

        float rs0 = 0.f, rs1 = 0.f;
        #pragma unroll
        for (int na = 0; na < 8; na++) {
            s[na][0] = __expf(s[na][0] - mn0); rs0 += s[na][0];
            s[na][1] = __expf(s[na][1] - mn0); rs0 += s[na][1];
            s[na][2] = __expf(s[na][2] - mn1); rs1 += s[na][2];
            s[na][3] = __expf(s[na][3] - mn1); rs1 += s[na][3];
        }
        rs0 += __shfl_xor_sync(0xffffffffu, rs0, 1);
        rs0 += __shfl_xor_sync(0xffffffffu, rs0, 2);
        rs1 += __shfl_xor_sync(0xffffffffu, rs1, 1);
        rs1 += __shfl_xor_sync(0xffffffffu, rs1, 2);
        l_0 = l_0 * al0 + rs0;
        l_1 = l_1 * al1 + rs1;

        #pragma unroll
        for (int na = 0; na < 8; na++) {
            o[na][0] *= al0; o[na][1] *= al0;
            o[na][2] *= al1; o[na][3] *= al1;
        }

        // ---- write P (tf32 bits) to smem (warp-private 16-row slab) ----
        __syncwarp();
        #pragma unroll
        for (int na = 0; na < 8; na++) {
            const int cb = na * 8 + 2 * (lane & 3);
            Pu[rloc * PSTR + cb]           = f2tf32(s[na][0]);
            Pu[rloc * PSTR + cb + 1]       = f2tf32(s[na][1]);
            Pu[(rloc + 8) * PSTR + cb]     = f2tf32(s[na][2]);
            Pu[(rloc + 8) * PSTR + cb + 1] = f2tf32(s[na][3]);
        }
        __syncwarp();

        // ---- O += P @ V ----
        #pragma unroll
        for (int ks = 0; ks < 8; ks++) {
            const int c = ks * 8 + (lane & 3);
            uint32_t pa[4];
            pa[0] = Pu[rloc * PSTR + c];
            pa[1] = Pu[(rloc + 8) * PSTR + c];
            pa[2] = Pu[rloc * PSTR + c + 4];
            pa[3] = Pu[(rloc + 8) * PSTR + c + 4];
            const int kv0 = ks * 8 + (lane & 3);
            #pragma unroll
            for (int na = 0; na < 8; na++) {
                const int nn = na * 8 + (lane >> 2);
                uint32_t b0 = f2tf32(Vs[kv0 * VSTR + nn]);
                uint32_t b1 = f2tf32(Vs[(kv0 + 4) * VSTR + nn]);
                mma_tf32(o[na], pa, b0, b1);
            }
        }
        __syncthreads();   // before next K/V overwrite
    }

    // ---- finalize: divide by l, write to g_AO[b][q][h*64+hd] ----
    const float inv0 = 1.0f / l_0;
    const float inv1 = 1.0f / l_1;
    #pragma unroll
    for (int na = 0; na < 8; na++) {
        const int col = h * HD_ + na * 8 + 2 * (lane & 3);
        *(float2*)(g_AO + ((size_t)b * NQ_ + q0) * D_ + col) =
            make_float2(o[na][0] * inv0, o[na][1] * inv0);
        *(float2*)(g_AO + ((size_t)b * NQ_ + q0 + 8) * D_ + col) =
            make_float2(o[na][2] * inv1, o[na][3] * inv1);
    }
}

// =======================================================================
// AO gather kernel feeding the final GEMM needs g_AO as input; expose a
// trivial device-pointer bridge kernel-side (no cudaGetSymbolAddress).
// The final GEMM reads its A operand from g_AO directly when A == nullptr.
// =======================================================================
__global__ __launch_bounds__(256, 2)
void gemm_tf32_out(const float* __restrict__ W, float* __restrict__ out)
{
    // thin wrapper: call pattern identical to gemm_tf32<3> with A = g_AO
    extern __shared__ float sm[];
    float* Asb[2] = { sm,              sm + 128 * GSTR };
    float* Bsb[2] = { sm + 2*128*GSTR, sm + 3*128*GSTR };

    const int tid  = threadIdx.x;
    const int lane = tid & 31;
    const int wid  = tid >> 5;
    const int wm   = wid >> 2;
    const int wn   = wid & 3;
    const int m0   = blockIdx.y * 128;
    const int n0   = blockIdx.x * 128;
    const float* A = g_AO;

    float acc[4][4][4];
    #pragma unroll
    for (int i = 0; i < 4; i++)
        #pragma unroll
        for (int j = 0; j < 4; j++)
            #pragma unroll
            for (int r = 0; r < 4; r++) acc[i][j][r] = 0.f;

    auto load_tiles = [&](int buf, int kt) {
        const float* Ag = A + (size_t)m0 * 512 + kt * 32;
        const float* Wg = W + (size_t)n0 * 512 + kt * 32;
        #pragma unroll
        for (int i = 0; i < 4; i++) {
            int idx = tid + i * 256;
            int row = idx >> 3, seg = idx & 7;
            cp16(&Asb[buf][row * GSTR + seg * 4], Ag + (size_t)row * 512 + seg * 4);
        }
        #pragma unroll
        for (int i = 0; i < 4; i++) {
            int idx = tid + i * 256;
            int row = idx >> 3, seg = idx & 7;
            cp16(&Bsb[buf][row * GSTR + seg * 4], Wg + (size_t)row * 512 + seg * 4);
        }
        CP_COMMIT();
    };

    load_tiles(0, 0);

    for (int kt = 0; kt < 16; kt++) {
        const int buf = kt & 1;
        if (kt + 1 < 16) {
            load_tiles(buf ^ 1, kt + 1);
            asm volatile("cp.async.wait_group 1;");
        } else {
            asm volatile("cp.async.wait_group 0;");
        }
        __syncthreads();

        const float* a_s = Asb[buf];
        const float* b_s = Bsb[buf];
        #pragma unroll
        for (int ks = 0; ks < 4; ks++) {
            uint32_t af[4][4], bf[4][2];
            const int c = ks * 8 + (lane & 3);
            #pragma unroll
            for (int ma = 0; ma < 4; ma++) {
                const int r = wm * 64 + ma * 16 + (lane >> 2);
                af[ma][0] = f2tf32(a_s[r * GSTR + c]);
                af[ma][1] = f2tf32(a_s[(r + 8) * GSTR + c]);
                af[ma][2] = f2tf32(a_s[r * GSTR + c + 4]);
                af[ma][3] = f2tf32(a_s[(r + 8) * GSTR + c + 4]);
            }
            #pragma unroll
            for (int na = 0; na < 4; na++) {
                const int nn = wn * 32 + na * 8 + (lane >> 2);
                bf[na][0] = f2tf32(b_s[nn * GSTR + c]);
                bf[na][1] = f2tf32(b_s[nn * GSTR + c + 4]);
            }
            #pragma unroll
            for (int ma = 0; ma < 4; ma++)
                #pragma unroll
                for (int na = 0; na < 4; na++)
                    mma_tf32(acc[ma][na], af[ma], bf[na][0], bf[na][1]);
        }
        __syncthreads();
    }

    #pragma unroll
    for (int ma = 0; ma < 4; ma++) {
        #pragma unroll
        for (int na = 0; na < 4; na++) {
            const int m = m0 + wm * 64 + ma * 16 + (lane >> 2);
            const int n = n0 + wn * 32 + na * 8 + 2 * (lane & 3);
            const float* a = acc[ma][na];
            *(float2*)(out + (size_t)m * 512 + n)       = make_float2(a[0], a[1]);
            *(float2*)(out + (size_t)(m + 8) * 512 + n) = make_float2(a[2], a[3]);
        }
    }
}

// =======================================================================
// launch
// =======================================================================
#define GEMM_SMEM (4 * 128 * GSTR * sizeof(float))          // 73728 B
#define ATT_SMEM  (ATT_SMEM_FLOATS * sizeof(float))         // 105472 B

extern "C" void kernel_launch(void* const* d_in, const int* in_sizes, int n_in,
                              void* d_out, int out_size)
{
    const float* x        = (const float*)d_in[0];
    const float* enc      = (const float*)d_in[1];
    const float* pos_bias = (const float*)d_in[2];
    const float* Wq       = (const float*)d_in[3];
    const float* Wk       = (const float*)d_in[4];
    const float* Wv       = (const float*)d_in[5];
    const float* Wo       = (const float*)d_in[6];
    float* out = (float*)d_out;

    cudaFuncSetAttribute(gemm_tf32<0>, cudaFuncAttributeMaxDynamicSharedMemorySize, GEMM_SMEM);
    cudaFuncSetAttribute(gemm_tf32<1>, cudaFuncAttributeMaxDynamicSharedMemorySize, GEMM_SMEM);
    cudaFuncSetAttribute(gemm_tf32<2>, cudaFuncAttributeMaxDynamicSharedMemorySize, GEMM_SMEM);
    cudaFuncSetAttribute(gemm_tf32_out, cudaFuncAttributeMaxDynamicSharedMemorySize, GEMM_SMEM);
    cudaFuncSetAttribute(attn_tf32,     cudaFuncAttributeMaxDynamicSharedMemorySize, ATT_SMEM);

    // Q projection: M = B*NQ = 8192 -> g_Q (head-split)
    gemm_tf32<0><<<dim3(4, 64), 256, GEMM_SMEM>>>(x,   Wq, nullptr, B_ * NQ_,  NQ_);
    // K, V projections: M = B*NKV = 16384 -> g_K, g_V (head-split)
    gemm_tf32<1><<<dim3(4, 128), 256, GEMM_SMEM>>>(enc, Wk, nullptr, B_ * NKV_, NKV_);
    gemm_tf32<2><<<dim3(4, 128), 256, GEMM_SMEM>>>(enc, Wv, nullptr, B_ * NKV_, NKV_);
    // attention
    attn_tf32<<<B_ * H_ * (NQ_ / 128), 256, ATT_SMEM>>>(pos_bias);
    // output projection (A = g_AO read device-side)
    gemm_tf32_out<<<dim3(4, 64), 256, GEMM_SMEM>>>(Wo, out);
}